// round 11
// baseline (speedup 1.0000x reference)
#include <cuda_runtime.h>
#include <cuda_fp16.h>
#include <cstdint>

namespace {

constexpr int NFREQ = 6;
constexpr int XS    = 88;   // X row stride in halves (conflict-free, 16B aligned)
constexpr int WS1   = 40;   // W1 row stride in halves
constexpr int BP    = 256;  // points per block in fused kernel

// Merged geo+col channel-interleaved fp16 planes: (H, W, 32), texel = 64B:
// [geo ch0-7][geo ch8-15][col ch0-7][col ch8-15] as 4x uint4.
__device__ __half g_tp[125829120];  // 252 MB

constexpr long long OFF_XY0 = 0LL;
constexpr long long OFF_XZ0 = 8388608LL;
constexpr long long OFF_YZ0 = 16777216LL;
constexpr long long OFF_XY1 = 25165824LL;
constexpr long long OFF_XZ1 = 58720256LL;
constexpr long long OFF_YZ1 = 92274688LL;

__device__ __forceinline__ unsigned packh2(float a, float b) {
  __half2 h = __floats2half2_rn(a, b);
  return *reinterpret_cast<unsigned*>(&h);
}

// ---------------- pack: one thread = two adjacent texels (float2 loads) ----------------
__device__ __forceinline__ void pack_body(const float* __restrict__ geo,
                                          const float* __restrict__ col,
                                          long long dstoff, int area, int pairIdx) {
  float2 v[32];
#pragma unroll
  for (int c = 0; c < 16; c++) {
    v[c]      = __ldg(reinterpret_cast<const float2*>(geo + (size_t)c * area) + pairIdx);
    v[16 + c] = __ldg(reinterpret_cast<const float2*>(col + (size_t)c * area) + pairIdx);
  }
  uint4* out = reinterpret_cast<uint4*>(g_tp + dstoff + (long long)pairIdx * 64);
#pragma unroll
  for (int k = 0; k < 4; k++) {
    out[k] = make_uint4(packh2(v[8 * k].x, v[8 * k + 1].x), packh2(v[8 * k + 2].x, v[8 * k + 3].x),
                        packh2(v[8 * k + 4].x, v[8 * k + 5].x), packh2(v[8 * k + 6].x, v[8 * k + 7].x));
  }
#pragma unroll
  for (int k = 0; k < 4; k++) {
    out[4 + k] = make_uint4(packh2(v[8 * k].y, v[8 * k + 1].y), packh2(v[8 * k + 2].y, v[8 * k + 3].y),
                            packh2(v[8 * k + 4].y, v[8 * k + 5].y), packh2(v[8 * k + 6].y, v[8 * k + 7].y));
  }
}

struct Pack3 { const float* geo[3]; const float* col[3]; };

// Three 512-plane pairs: 1024 blocks each (131072 texel-pairs / 128 threads).
__global__ __launch_bounds__(128) void pack512_all(Pack3 PP) {
  int pi = blockIdx.x >> 10;
  int lb = blockIdx.x & 1023;
  long long dst = (pi == 0) ? OFF_XY0 : (pi == 1 ? OFF_XZ0 : OFF_YZ0);
  pack_body(PP.geo[pi], PP.col[pi], dst, 262144, lb * 128 + threadIdx.x);
}

// Three 1024-plane pairs: 4096 blocks each (uniform work per block).
__global__ __launch_bounds__(128) void pack1024_all(Pack3 PP) {
  int pi = blockIdx.x >> 12;
  int lb = blockIdx.x & 4095;
  long long dst = (pi == 0) ? OFF_XY1 : (pi == 1 ? OFF_XZ1 : OFF_YZ1);
  pack_body(PP.geo[pi], PP.col[pi], dst, 1048576, lb * 128 + threadIdx.x);
}

// ---------------- gather helpers ----------------
template <int R>
__device__ __forceinline__ void corners(float gx, float gy, int* o, float* w) {
  const float rm1 = (float)(R - 1);
  float ix = fminf(fmaxf((gx + 1.0f) * 0.5f * rm1, 0.0f), rm1);
  float iy = fminf(fmaxf((gy + 1.0f) * 0.5f * rm1, 0.0f), rm1);
  float fx0 = floorf(ix), fy0 = floorf(iy);
  int x0 = (int)fx0, y0 = (int)fy0;
  int x1 = min(x0 + 1, R - 1);
  int y1 = min(y0 + 1, R - 1);
  float wx = ix - fx0, wy = iy - fy0;
  w[0] = (1.0f - wx) * (1.0f - wy);
  w[1] = wx * (1.0f - wy);
  w[2] = (1.0f - wx) * wy;
  w[3] = wx * wy;
  o[0] = y0 * R + x0; o[1] = y0 * R + x1;
  o[2] = y1 * R + x0; o[3] = y1 * R + x1;
}

__device__ __forceinline__ void acc8q(uint4 v, float w, float* acc) {
  const __half2* h = reinterpret_cast<const __half2*>(&v);
#pragma unroll
  for (int k = 0; k < 4; k++) {
    float2 f = __half22float2(h[k]);
    acc[2 * k]     += w * f.x;
    acc[2 * k + 1] += w * f.y;
  }
}

// One level (3 planes): issue all 12 corner loads, then accumulate.
template <int R>
__device__ __forceinline__ void sample_level(const __half* p0, const __half* p1,
                                             const __half* p2,
                                             float nx, float ny, float nz,
                                             int r, float* acc) {
  int o[12];
  float w[12];
  corners<R>(nx, ny, o + 0, w + 0);
  corners<R>(nx, nz, o + 4, w + 4);
  corners<R>(ny, nz, o + 8, w + 8);
  uint4 v[12];
#pragma unroll
  for (int k = 0; k < 4; k++)
    v[k] = __ldg(reinterpret_cast<const uint4*>(p0 + ((size_t)o[k] << 5)) + r);
#pragma unroll
  for (int k = 0; k < 4; k++)
    v[4 + k] = __ldg(reinterpret_cast<const uint4*>(p1 + ((size_t)o[4 + k] << 5)) + r);
#pragma unroll
  for (int k = 0; k < 4; k++)
    v[8 + k] = __ldg(reinterpret_cast<const uint4*>(p2 + ((size_t)o[8 + k] << 5)) + r);
#pragma unroll
  for (int k = 0; k < 12; k++) acc8q(v[k], w[k], acc);
}

__device__ __forceinline__ uint4 pack8f(const float* a) {
  return make_uint4(packh2(a[0], a[1]), packh2(a[2], a[3]),
                    packh2(a[4], a[5]), packh2(a[6], a[7]));
}

// ---------------- fused decode ----------------
struct MlpP {
  const float* p;
  const float* bound;
  const float* W0;  const float* b0;
  const float* W1;  const float* b1;
  const float* Wo;  const float* bo;
  const float* cW0; const float* cb0;
  const float* cW1; const float* cb1;
  const float* cWo; const float* cbo;
  float* out;
  int N;
};

__device__ __forceinline__ void mma16816(float* d, const unsigned* a,
                                         unsigned b0, unsigned b1) {
  asm volatile(
      "mma.sync.aligned.m16n8k16.row.col.f32.f16.f16.f32 "
      "{%0,%1,%2,%3}, {%4,%5,%6,%7}, {%8,%9}, {%0,%1,%2,%3};"
      : "+f"(d[0]), "+f"(d[1]), "+f"(d[2]), "+f"(d[3])
      : "r"(a[0]), "r"(a[1]), "r"(a[2]), "r"(a[3]), "r"(b0), "r"(b1));
}

__device__ __forceinline__ void two_layer(const __half* X, const __half* W0s,
                                          const float* b0v, const __half* W1s,
                                          int rb, int g, int q,
                                          float acc2[2][4][4]) {
  float acc[2][4][4];
#pragma unroll
  for (int i = 0; i < 2; i++)
#pragma unroll
    for (int j = 0; j < 4; j++)
#pragma unroll
      for (int k = 0; k < 4; k++) acc[i][j][k] = 0.0f;

#pragma unroll
  for (int tk = 0; tk < 5; tk++) {
    unsigned a[2][4];
#pragma unroll
    for (int i = 0; i < 2; i++) {
      const __half* base = X + (rb + i * 16 + g) * XS + tk * 16 + q * 2;
      a[i][0] = *reinterpret_cast<const unsigned*>(base);
      a[i][1] = *reinterpret_cast<const unsigned*>(base + 8 * XS);
      a[i][2] = *reinterpret_cast<const unsigned*>(base + 8);
      a[i][3] = *reinterpret_cast<const unsigned*>(base + 8 * XS + 8);
    }
#pragma unroll
    for (int j = 0; j < 4; j++) {
      const __half* wb = W0s + (j * 8 + g) * XS + tk * 16 + q * 2;
      unsigned br0 = *reinterpret_cast<const unsigned*>(wb);
      unsigned br1 = *reinterpret_cast<const unsigned*>(wb + 8);
      mma16816(acc[0][j], a[0], br0, br1);
      mma16816(acc[1][j], a[1], br0, br1);
    }
  }

  float bj0[4], bj1[4];
#pragma unroll
  for (int j = 0; j < 4; j++) { bj0[j] = b0v[j * 8 + q * 2]; bj1[j] = b0v[j * 8 + q * 2 + 1]; }

#pragma unroll
  for (int i = 0; i < 2; i++)
#pragma unroll
    for (int j = 0; j < 4; j++)
#pragma unroll
      for (int k = 0; k < 4; k++) acc2[i][j][k] = 0.0f;

#pragma unroll
  for (int i = 0; i < 2; i++) {
    unsigned a2[2][4];
#pragma unroll
    for (int tk = 0; tk < 2; tk++) {
      int j0 = 2 * tk, j1 = j0 + 1;
      a2[tk][0] = packh2(fmaxf(acc[i][j0][0] + bj0[j0], 0.0f),
                         fmaxf(acc[i][j0][1] + bj1[j0], 0.0f));
      a2[tk][1] = packh2(fmaxf(acc[i][j0][2] + bj0[j0], 0.0f),
                         fmaxf(acc[i][j0][3] + bj1[j0], 0.0f));
      a2[tk][2] = packh2(fmaxf(acc[i][j1][0] + bj0[j1], 0.0f),
                         fmaxf(acc[i][j1][1] + bj1[j1], 0.0f));
      a2[tk][3] = packh2(fmaxf(acc[i][j1][2] + bj0[j1], 0.0f),
                         fmaxf(acc[i][j1][3] + bj1[j1], 0.0f));
    }
#pragma unroll
    for (int j = 0; j < 4; j++)
#pragma unroll
      for (int tk = 0; tk < 2; tk++) {
        const __half* wb = W1s + (j * 8 + g) * WS1 + tk * 16 + q * 2;
        mma16816(acc2[i][j], a2[tk],
                 *reinterpret_cast<const unsigned*>(wb),
                 *reinterpret_cast<const unsigned*>(wb + 8));
      }
  }
}

__device__ __forceinline__ void out_dots(const float acc2[2][4][4], const float* b1v,
                                         const float* wvec, int q, float res[2][2]) {
#pragma unroll
  for (int i = 0; i < 2; i++) { res[i][0] = 0.0f; res[i][1] = 0.0f; }
#pragma unroll
  for (int i = 0; i < 2; i++)
#pragma unroll
    for (int j = 0; j < 4; j++) {
      int c0 = j * 8 + q * 2, c1 = c0 + 1;
      float h00 = fmaxf(acc2[i][j][0] + b1v[c0], 0.0f);
      float h01 = fmaxf(acc2[i][j][1] + b1v[c1], 0.0f);
      float h10 = fmaxf(acc2[i][j][2] + b1v[c0], 0.0f);
      float h11 = fmaxf(acc2[i][j][3] + b1v[c1], 0.0f);
      res[i][0] += wvec[c0] * h00 + wvec[c1] * h01;
      res[i][1] += wvec[c0] * h10 + wvec[c1] * h11;
    }
#pragma unroll
  for (int i = 0; i < 2; i++)
#pragma unroll
    for (int k = 0; k < 2; k++) {
      res[i][k] += __shfl_xor_sync(0xffffffffu, res[i][k], 1);
      res[i][k] += __shfl_xor_sync(0xffffffffu, res[i][k], 2);
    }
}

__global__ __launch_bounds__(BP, 2) void decode_kernel(MlpP P) {
  extern __shared__ __align__(16) char dsm[];
  __half* Xg   = reinterpret_cast<__half*>(dsm);             // BP*XS
  __half* Xc   = Xg + BP * XS;                               // BP*XS
  __half* W0s  = Xc + BP * XS;                               // 32*XS
  __half* cW0s = W0s + 32 * XS;
  __half* W1s  = cW0s + 32 * XS;                             // 32*WS1
  __half* cW1s = W1s + 32 * WS1;
  float* fb    = reinterpret_cast<float*>(cW1s + 32 * WS1);
  float* sb0 = fb;        float* sb1 = fb + 32;  float* sWo = fb + 64;
  float* scb0 = fb + 96;  float* scb1 = fb + 128; float* scWo = fb + 160;  // 96
  float* sext = fb + 256;  // [0]=bo, [1..3]=cbo

  const int t = threadIdx.x;
  // weights: input cols 0..38 = emb, 39 = pad, 40..71 = features, 72..87 = pad
  for (int i = t; i < 32 * XS; i += BP) {
    int j = i / XS, c = i % XS;
    float w0v = 0.0f, cw0v = 0.0f;
    if (c < 39)                 { w0v = P.W0[j * 71 + c];     cw0v = P.cW0[j * 71 + c]; }
    else if (c >= 40 && c < 72) { w0v = P.W0[j * 71 + c - 1]; cw0v = P.cW0[j * 71 + c - 1]; }
    W0s[i] = __float2half(w0v);
    cW0s[i] = __float2half(cw0v);
  }
  for (int i = t; i < 32 * WS1; i += BP) {
    int j = i / WS1, c = i % WS1;
    W1s[i]  = __float2half(c < 32 ? P.W1[j * 32 + c]  : 0.0f);
    cW1s[i] = __float2half(c < 32 ? P.cW1[j * 32 + c] : 0.0f);
  }
  if (t < 32) {
    sb0[t] = P.b0[t]; sb1[t] = P.b1[t]; sWo[t] = P.Wo[t];
    scb0[t] = P.cb0[t]; scb1[t] = P.cb1[t];
  }
  for (int i = t; i < 96; i += BP) scWo[i] = P.cWo[i];
  if (t == 0) sext[0] = P.bo[0];
  if (t < 3) sext[1 + t] = P.cbo[t];

  const float lo0 = __ldg(P.bound + 0), hi0 = __ldg(P.bound + 1);
  const float lo1 = __ldg(P.bound + 2), hi1 = __ldg(P.bound + 3);
  const float lo2 = __ldg(P.bound + 4), hi2 = __ldg(P.bound + 5);
  const int blockbase = blockIdx.x * BP;

  // ---- phase 1a: per-thread embedding row (chunks 0..4; pads 9,10) ----
  {
    const int idx = blockbase + t;
    uint4* rg = reinterpret_cast<uint4*>(Xg + t * XS);
    uint4* rc = reinterpret_cast<uint4*>(Xc + t * XS);
    uint4 z = make_uint4(0, 0, 0, 0);
    if (idx < P.N) {
      float x[40];
      x[0] = (P.p[3 * idx + 0] - lo0) / (hi0 - lo0);
      x[1] = (P.p[3 * idx + 1] - lo1) / (hi1 - lo1);
      x[2] = (P.p[3 * idx + 2] - lo2) / (hi2 - lo2);
#pragma unroll
      for (int a = 0; a < 3; a++) {
        float s, c;
        sincosf(x[a] * 3.14159265358979323846f, &s, &c);
        x[3 + a] = s;
        x[21 + a] = c;
#pragma unroll
        for (int f = 1; f < NFREQ; f++) {
          float s2 = 2.0f * s * c;
          float c2 = 1.0f - 2.0f * s * s;
          x[3 + f * 3 + a] = s2;
          x[21 + f * 3 + a] = c2;
          s = s2; c = c2;
        }
      }
      x[39] = 0.0f;
#pragma unroll
      for (int w = 0; w < 5; w++) {
        uint4 v = make_uint4(packh2(x[8 * w], x[8 * w + 1]), packh2(x[8 * w + 2], x[8 * w + 3]),
                             packh2(x[8 * w + 4], x[8 * w + 5]), packh2(x[8 * w + 6], x[8 * w + 7]));
        rg[w] = v; rc[w] = v;
      }
    } else {
#pragma unroll
      for (int w = 0; w < 9; w++) { rg[w] = z; rc[w] = z; }
    }
    rg[9] = z; rg[10] = z; rc[9] = z; rc[10] = z;
  }

  // ---- phase 1b: quad-cooperative gather, batched loads per level ----
  {
    const int r = t & 3;
#pragma unroll
    for (int pass = 0; pass < 4; pass++) {
      const int j = pass * 64 + (t >> 2);
      const int pidx = blockbase + j;
      if (pidx < P.N) {
        float nx = (__ldg(P.p + 3 * pidx + 0) - lo0) / (hi0 - lo0);
        float ny = (__ldg(P.p + 3 * pidx + 1) - lo1) / (hi1 - lo1);
        float nz = (__ldg(P.p + 3 * pidx + 2) - lo2) / (hi2 - lo2);
        __half* row = ((r < 2) ? Xg : Xc) + j * XS;
        float acc[8];
#pragma unroll
        for (int k = 0; k < 8; k++) acc[k] = 0.0f;
        sample_level<512>(g_tp + OFF_XY0, g_tp + OFF_XZ0, g_tp + OFF_YZ0,
                          nx, ny, nz, r, acc);
        *reinterpret_cast<uint4*>(row + 40 + 8 * (r & 1)) = pack8f(acc);
#pragma unroll
        for (int k = 0; k < 8; k++) acc[k] = 0.0f;
        sample_level<1024>(g_tp + OFF_XY1, g_tp + OFF_XZ1, g_tp + OFF_YZ1,
                           nx, ny, nz, r, acc);
        *reinterpret_cast<uint4*>(row + 56 + 8 * (r & 1)) = pack8f(acc);
      }
    }
  }
  __syncthreads();

  // ---- phase 2: tensor-core GEMMs (8 warps x 32 rows) ----
  const int wid = t >> 5, lane = t & 31, g = lane >> 2, q = lane & 3;
  const int rb = wid * 32;

  float sdfv[2][2], rv[2][2], gv[2][2], bv[2][2];
  {
    float acc2[2][4][4];
    two_layer(Xg, W0s, sb0, W1s, rb, g, q, acc2);
    out_dots(acc2, sb1, sWo, q, sdfv);
#pragma unroll
    for (int i = 0; i < 2; i++)
#pragma unroll
      for (int k = 0; k < 2; k++) sdfv[i][k] = tanhf(sdfv[i][k] + sext[0]);
  }
  {
    float acc2[2][4][4];
    two_layer(Xc, cW0s, scb0, cW1s, rb, g, q, acc2);
    out_dots(acc2, scb1, scWo + 0,  q, rv);
    out_dots(acc2, scb1, scWo + 32, q, gv);
    out_dots(acc2, scb1, scWo + 64, q, bv);
  }

  if (q == 0) {
    float4* out4 = reinterpret_cast<float4*>(P.out);
#pragma unroll
    for (int i = 0; i < 2; i++) {
      int r0 = blockbase + rb + i * 16 + g;
      if (r0 < P.N)
        out4[r0] = make_float4(rv[i][0] + sext[1], gv[i][0] + sext[2],
                               bv[i][0] + sext[3], sdfv[i][0]);
      if (r0 + 8 < P.N)
        out4[r0 + 8] = make_float4(rv[i][1] + sext[1], gv[i][1] + sext[2],
                                   bv[i][1] + sext[3], sdfv[i][1]);
    }
  }
}

constexpr int DEC_SMEM = (2 * BP * XS + 2 * 32 * XS + 2 * 32 * WS1) * 2 + 260 * 4;

}  // namespace

extern "C" void kernel_launch(void* const* d_in, const int* in_sizes, int n_in,
                              void* d_out, int out_size) {
  Pack3 P512, P1024;
  for (int i = 0; i < 3; i++) {
    P512.geo[i]  = (const float*)d_in[2 + i];
    P512.col[i]  = (const float*)d_in[8 + i];
    P1024.geo[i] = (const float*)d_in[5 + i];
    P1024.col[i] = (const float*)d_in[11 + i];
  }
  pack512_all<<<3072, 128>>>(P512);
  pack1024_all<<<12288, 128>>>(P1024);

  const float* p = (const float*)d_in[0];
  const float* bound = (const float*)d_in[1];
  int N = in_sizes[0] / 3;

  MlpP P;
  P.p = p; P.bound = bound;
  P.W0  = (const float*)d_in[14]; P.b0  = (const float*)d_in[15];
  P.W1  = (const float*)d_in[16]; P.b1  = (const float*)d_in[17];
  P.Wo  = (const float*)d_in[18]; P.bo  = (const float*)d_in[19];
  P.cW0 = (const float*)d_in[20]; P.cb0 = (const float*)d_in[21];
  P.cW1 = (const float*)d_in[22]; P.cb1 = (const float*)d_in[23];
  P.cWo = (const float*)d_in[24]; P.cbo = (const float*)d_in[25];
  P.out = (float*)d_out;
  P.N = N;

  cudaFuncSetAttribute(decode_kernel, cudaFuncAttributeMaxDynamicSharedMemorySize, DEC_SMEM);
  decode_kernel<<<(N + BP - 1) / BP, BP, DEC_SMEM>>>(P);
}

// round 12
// speedup vs baseline: 1.3489x; 1.3489x over previous
#include <cuda_runtime.h>
#include <cuda_fp16.h>
#include <cstdint>

namespace {

constexpr int NFREQ = 6;
constexpr int XS    = 88;   // X row stride in halves (conflict-free, 16B aligned)
constexpr int WS1   = 40;   // W1 row stride in halves
constexpr int BP    = 256;  // points per block in decode kernel
constexpr int NMAX  = 1048576;

// Merged geo+col channel-interleaved fp16 planes: (H, W, 32), texel = 64B:
// [geo ch0-7][geo ch8-15][col ch0-7][col ch8-15] as 4x uint4.
__device__ __half g_tp[125829120];  // 252 MB
// Feature scratch: [chunk 0..7][point] as uint4 (8 fp16 each).
// chunks 0,1 = L0 geo; 2,3 = L0 col; 4,5 = L1 geo; 6,7 = L1 col.
__device__ uint4 g_feat4[8 * NMAX];  // 128 MB

constexpr long long OFF_XY0 = 0LL;
constexpr long long OFF_XZ0 = 8388608LL;
constexpr long long OFF_YZ0 = 16777216LL;
constexpr long long OFF_XY1 = 25165824LL;
constexpr long long OFF_XZ1 = 58720256LL;
constexpr long long OFF_YZ1 = 92274688LL;

__device__ __forceinline__ unsigned packh2(float a, float b) {
  __half2 h = __floats2half2_rn(a, b);
  return *reinterpret_cast<unsigned*>(&h);
}

// ---------------- pack: smem-free, one thread = one texel (R10, measured best) ----------------
__device__ __forceinline__ void pack_body(const float* __restrict__ geo,
                                          const float* __restrict__ col,
                                          long long dstoff, int area, int tex) {
  float v[32];
#pragma unroll
  for (int c = 0; c < 16; c++) {
    v[c]      = __ldg(geo + (size_t)c * area + tex);
    v[16 + c] = __ldg(col + (size_t)c * area + tex);
  }
  uint4* out = reinterpret_cast<uint4*>(g_tp + dstoff + (long long)tex * 32);
#pragma unroll
  for (int k = 0; k < 4; k++) {
    out[k] = make_uint4(packh2(v[8 * k], v[8 * k + 1]), packh2(v[8 * k + 2], v[8 * k + 3]),
                        packh2(v[8 * k + 4], v[8 * k + 5]), packh2(v[8 * k + 6], v[8 * k + 7]));
  }
}

struct Pack3 { const float* geo[3]; const float* col[3]; };

__global__ __launch_bounds__(128) void pack512_all(Pack3 PP) {
  int pi = blockIdx.x >> 11;
  int lb = blockIdx.x & 2047;
  long long dst = (pi == 0) ? OFF_XY0 : (pi == 1 ? OFF_XZ0 : OFF_YZ0);
  pack_body(PP.geo[pi], PP.col[pi], dst, 262144, lb * 128 + threadIdx.x);
}

__global__ __launch_bounds__(128) void pack_pair(const float* __restrict__ geo,
                                                 const float* __restrict__ col,
                                                 long long dstoff, int area) {
  pack_body(geo, col, dstoff, area, blockIdx.x * 128 + threadIdx.x);
}

// ---------------- quad-cooperative gather (standalone, high occupancy) ----------------
__device__ __forceinline__ void acc8q(uint4 v, float w, float* acc) {
  const __half2* h = reinterpret_cast<const __half2*>(&v);
#pragma unroll
  for (int k = 0; k < 4; k++) {
    float2 f = __half22float2(h[k]);
    acc[2 * k]     += w * f.x;
    acc[2 * k + 1] += w * f.y;
  }
}

template <int R>
__device__ __forceinline__ void sample_quad(const __half* __restrict__ pl,
                                            float gx, float gy, int r, float* acc) {
  const float rm1 = (float)(R - 1);
  float ix = fminf(fmaxf((gx + 1.0f) * 0.5f * rm1, 0.0f), rm1);
  float iy = fminf(fmaxf((gy + 1.0f) * 0.5f * rm1, 0.0f), rm1);
  float fx0 = floorf(ix), fy0 = floorf(iy);
  int x0 = (int)fx0, y0 = (int)fy0;
  int x1 = min(x0 + 1, R - 1);
  int y1 = min(y0 + 1, R - 1);
  float wx = ix - fx0, wy = iy - fy0;
  float w[4] = {(1.0f - wx) * (1.0f - wy), wx * (1.0f - wy),
                (1.0f - wx) * wy,          wx * wy};
  int o[4] = {y0 * R + x0, y0 * R + x1, y1 * R + x0, y1 * R + x1};
  uint4 v[4];
#pragma unroll
  for (int k = 0; k < 4; k++)
    v[k] = __ldg(reinterpret_cast<const uint4*>(pl + ((size_t)o[k] << 5)) + r);
#pragma unroll
  for (int k = 0; k < 4; k++) acc8q(v[k], w[k], acc);
}

__device__ __forceinline__ uint4 pack8f(const float* a) {
  return make_uint4(packh2(a[0], a[1]), packh2(a[2], a[3]),
                    packh2(a[4], a[5]), packh2(a[6], a[7]));
}

// launch_bounds(256, 4): cap regs at 64 -> 32 warps/SM for latency hiding.
__global__ __launch_bounds__(256, 4) void gather_kernel(const float* __restrict__ p,
                                                        const float* __restrict__ bound,
                                                        int N) {
  const int tid = blockIdx.x * 256 + threadIdx.x;
  const int idx = tid >> 2;
  const int r = tid & 3;
  if (idx >= N) return;

  float lo0 = __ldg(bound + 0), hi0 = __ldg(bound + 1);
  float lo1 = __ldg(bound + 2), hi1 = __ldg(bound + 3);
  float lo2 = __ldg(bound + 4), hi2 = __ldg(bound + 5);
  float nx = (__ldg(p + 3 * idx + 0) - lo0) / (hi0 - lo0);
  float ny = (__ldg(p + 3 * idx + 1) - lo1) / (hi1 - lo1);
  float nz = (__ldg(p + 3 * idx + 2) - lo2) / (hi2 - lo2);

  float acc[8];
#pragma unroll
  for (int k = 0; k < 8; k++) acc[k] = 0.0f;
  sample_quad<512>(g_tp + OFF_XY0, nx, ny, r, acc);
  sample_quad<512>(g_tp + OFF_XZ0, nx, nz, r, acc);
  sample_quad<512>(g_tp + OFF_YZ0, ny, nz, r, acc);
  g_feat4[r * N + idx] = pack8f(acc);

#pragma unroll
  for (int k = 0; k < 8; k++) acc[k] = 0.0f;
  sample_quad<1024>(g_tp + OFF_XY1, nx, ny, r, acc);
  sample_quad<1024>(g_tp + OFF_XZ1, nx, nz, r, acc);
  sample_quad<1024>(g_tp + OFF_YZ1, ny, nz, r, acc);
  g_feat4[(4 + r) * N + idx] = pack8f(acc);
}

// ---------------- decode: embedding + scratch load + tensor-core MLP ----------------
struct MlpP {
  const float* p;
  const float* bound;
  const float* W0;  const float* b0;
  const float* W1;  const float* b1;
  const float* Wo;  const float* bo;
  const float* cW0; const float* cb0;
  const float* cW1; const float* cb1;
  const float* cWo; const float* cbo;
  float* out;
  int N;
};

__device__ __forceinline__ void mma16816(float* d, const unsigned* a,
                                         unsigned b0, unsigned b1) {
  asm volatile(
      "mma.sync.aligned.m16n8k16.row.col.f32.f16.f16.f32 "
      "{%0,%1,%2,%3}, {%4,%5,%6,%7}, {%8,%9}, {%0,%1,%2,%3};"
      : "+f"(d[0]), "+f"(d[1]), "+f"(d[2]), "+f"(d[3])
      : "r"(a[0]), "r"(a[1]), "r"(a[2]), "r"(a[3]), "r"(b0), "r"(b1));
}

__device__ __forceinline__ void two_layer(const __half* X, const __half* W0s,
                                          const float* b0v, const __half* W1s,
                                          int rb, int g, int q,
                                          float acc2[2][4][4]) {
  float acc[2][4][4];
#pragma unroll
  for (int i = 0; i < 2; i++)
#pragma unroll
    for (int j = 0; j < 4; j++)
#pragma unroll
      for (int k = 0; k < 4; k++) acc[i][j][k] = 0.0f;

#pragma unroll
  for (int tk = 0; tk < 5; tk++) {
    unsigned a[2][4];
#pragma unroll
    for (int i = 0; i < 2; i++) {
      const __half* base = X + (rb + i * 16 + g) * XS + tk * 16 + q * 2;
      a[i][0] = *reinterpret_cast<const unsigned*>(base);
      a[i][1] = *reinterpret_cast<const unsigned*>(base + 8 * XS);
      a[i][2] = *reinterpret_cast<const unsigned*>(base + 8);
      a[i][3] = *reinterpret_cast<const unsigned*>(base + 8 * XS + 8);
    }
#pragma unroll
    for (int j = 0; j < 4; j++) {
      const __half* wb = W0s + (j * 8 + g) * XS + tk * 16 + q * 2;
      unsigned br0 = *reinterpret_cast<const unsigned*>(wb);
      unsigned br1 = *reinterpret_cast<const unsigned*>(wb + 8);
      mma16816(acc[0][j], a[0], br0, br1);
      mma16816(acc[1][j], a[1], br0, br1);
    }
  }

  float bj0[4], bj1[4];
#pragma unroll
  for (int j = 0; j < 4; j++) { bj0[j] = b0v[j * 8 + q * 2]; bj1[j] = b0v[j * 8 + q * 2 + 1]; }

#pragma unroll
  for (int i = 0; i < 2; i++)
#pragma unroll
    for (int j = 0; j < 4; j++)
#pragma unroll
      for (int k = 0; k < 4; k++) acc2[i][j][k] = 0.0f;

#pragma unroll
  for (int i = 0; i < 2; i++) {
    unsigned a2[2][4];
#pragma unroll
    for (int tk = 0; tk < 2; tk++) {
      int j0 = 2 * tk, j1 = j0 + 1;
      a2[tk][0] = packh2(fmaxf(acc[i][j0][0] + bj0[j0], 0.0f),
                         fmaxf(acc[i][j0][1] + bj1[j0], 0.0f));
      a2[tk][1] = packh2(fmaxf(acc[i][j0][2] + bj0[j0], 0.0f),
                         fmaxf(acc[i][j0][3] + bj1[j0], 0.0f));
      a2[tk][2] = packh2(fmaxf(acc[i][j1][0] + bj0[j1], 0.0f),
                         fmaxf(acc[i][j1][1] + bj1[j1], 0.0f));
      a2[tk][3] = packh2(fmaxf(acc[i][j1][2] + bj0[j1], 0.0f),
                         fmaxf(acc[i][j1][3] + bj1[j1], 0.0f));
    }
#pragma unroll
    for (int j = 0; j < 4; j++)
#pragma unroll
      for (int tk = 0; tk < 2; tk++) {
        const __half* wb = W1s + (j * 8 + g) * WS1 + tk * 16 + q * 2;
        mma16816(acc2[i][j], a2[tk],
                 *reinterpret_cast<const unsigned*>(wb),
                 *reinterpret_cast<const unsigned*>(wb + 8));
      }
  }
}

__device__ __forceinline__ void out_dots(const float acc2[2][4][4], const float* b1v,
                                         const float* wvec, int q, float res[2][2]) {
#pragma unroll
  for (int i = 0; i < 2; i++) { res[i][0] = 0.0f; res[i][1] = 0.0f; }
#pragma unroll
  for (int i = 0; i < 2; i++)
#pragma unroll
    for (int j = 0; j < 4; j++) {
      int c0 = j * 8 + q * 2, c1 = c0 + 1;
      float h00 = fmaxf(acc2[i][j][0] + b1v[c0], 0.0f);
      float h01 = fmaxf(acc2[i][j][1] + b1v[c1], 0.0f);
      float h10 = fmaxf(acc2[i][j][2] + b1v[c0], 0.0f);
      float h11 = fmaxf(acc2[i][j][3] + b1v[c1], 0.0f);
      res[i][0] += wvec[c0] * h00 + wvec[c1] * h01;
      res[i][1] += wvec[c0] * h10 + wvec[c1] * h11;
    }
#pragma unroll
  for (int i = 0; i < 2; i++)
#pragma unroll
    for (int k = 0; k < 2; k++) {
      res[i][k] += __shfl_xor_sync(0xffffffffu, res[i][k], 1);
      res[i][k] += __shfl_xor_sync(0xffffffffu, res[i][k], 2);
    }
}

__global__ __launch_bounds__(BP, 2) void decode_kernel(MlpP P) {
  extern __shared__ __align__(16) char dsm[];
  __half* Xg   = reinterpret_cast<__half*>(dsm);             // BP*XS
  __half* Xc   = Xg + BP * XS;                               // BP*XS
  __half* W0s  = Xc + BP * XS;                               // 32*XS
  __half* cW0s = W0s + 32 * XS;
  __half* W1s  = cW0s + 32 * XS;                             // 32*WS1
  __half* cW1s = W1s + 32 * WS1;
  float* fb    = reinterpret_cast<float*>(cW1s + 32 * WS1);
  float* sb0 = fb;        float* sb1 = fb + 32;  float* sWo = fb + 64;
  float* scb0 = fb + 96;  float* scb1 = fb + 128; float* scWo = fb + 160;  // 96
  float* sext = fb + 256;  // [0]=bo, [1..3]=cbo

  const int t = threadIdx.x;
  // weights: input cols 0..38 = emb, 39 = pad, 40..71 = features, 72..87 = pad
  for (int i = t; i < 32 * XS; i += BP) {
    int j = i / XS, c = i % XS;
    float w0v = 0.0f, cw0v = 0.0f;
    if (c < 39)                 { w0v = P.W0[j * 71 + c];     cw0v = P.cW0[j * 71 + c]; }
    else if (c >= 40 && c < 72) { w0v = P.W0[j * 71 + c - 1]; cw0v = P.cW0[j * 71 + c - 1]; }
    W0s[i] = __float2half(w0v);
    cW0s[i] = __float2half(cw0v);
  }
  for (int i = t; i < 32 * WS1; i += BP) {
    int j = i / WS1, c = i % WS1;
    W1s[i]  = __float2half(c < 32 ? P.W1[j * 32 + c]  : 0.0f);
    cW1s[i] = __float2half(c < 32 ? P.cW1[j * 32 + c] : 0.0f);
  }
  if (t < 32) {
    sb0[t] = P.b0[t]; sb1[t] = P.b1[t]; sWo[t] = P.Wo[t];
    scb0[t] = P.cb0[t]; scb1[t] = P.cb1[t];
  }
  for (int i = t; i < 96; i += BP) scWo[i] = P.cWo[i];
  if (t == 0) sext[0] = P.bo[0];
  if (t < 3) sext[1 + t] = P.cbo[t];

  const float lo0 = __ldg(P.bound + 0), hi0 = __ldg(P.bound + 1);
  const float lo1 = __ldg(P.bound + 2), hi1 = __ldg(P.bound + 3);
  const float lo2 = __ldg(P.bound + 4), hi2 = __ldg(P.bound + 5);
  const int blockbase = blockIdx.x * BP;

  // ---- phase 1: embedding + coalesced feature-chunk loads ----
  {
    const int idx = blockbase + t;
    uint4* rg = reinterpret_cast<uint4*>(Xg + t * XS);
    uint4* rc = reinterpret_cast<uint4*>(Xc + t * XS);
    uint4 z = make_uint4(0, 0, 0, 0);
    if (idx < P.N) {
      float x[40];
      x[0] = (P.p[3 * idx + 0] - lo0) / (hi0 - lo0);
      x[1] = (P.p[3 * idx + 1] - lo1) / (hi1 - lo1);
      x[2] = (P.p[3 * idx + 2] - lo2) / (hi2 - lo2);
#pragma unroll
      for (int a = 0; a < 3; a++) {
        float s, c;
        sincosf(x[a] * 3.14159265358979323846f, &s, &c);
        x[3 + a] = s;
        x[21 + a] = c;
#pragma unroll
        for (int f = 1; f < NFREQ; f++) {
          float s2 = 2.0f * s * c;
          float c2 = 1.0f - 2.0f * s * s;
          x[3 + f * 3 + a] = s2;
          x[21 + f * 3 + a] = c2;
          s = s2; c = c2;
        }
      }
      x[39] = 0.0f;
#pragma unroll
      for (int w = 0; w < 5; w++) {
        uint4 v = make_uint4(packh2(x[8 * w], x[8 * w + 1]), packh2(x[8 * w + 2], x[8 * w + 3]),
                             packh2(x[8 * w + 4], x[8 * w + 5]), packh2(x[8 * w + 6], x[8 * w + 7]));
        rg[w] = v; rc[w] = v;
      }
      rg[5] = g_feat4[0 * P.N + idx];
      rg[6] = g_feat4[1 * P.N + idx];
      rg[7] = g_feat4[4 * P.N + idx];
      rg[8] = g_feat4[5 * P.N + idx];
      rc[5] = g_feat4[2 * P.N + idx];
      rc[6] = g_feat4[3 * P.N + idx];
      rc[7] = g_feat4[6 * P.N + idx];
      rc[8] = g_feat4[7 * P.N + idx];
    } else {
#pragma unroll
      for (int w = 0; w < 9; w++) { rg[w] = z; rc[w] = z; }
    }
    rg[9] = z; rg[10] = z; rc[9] = z; rc[10] = z;
  }
  __syncthreads();

  // ---- phase 2: tensor-core GEMMs (8 warps x 32 rows) ----
  const int wid = t >> 5, lane = t & 31, g = lane >> 2, q = lane & 3;
  const int rb = wid * 32;

  float sdfv[2][2], rv[2][2], gv[2][2], bv[2][2];
  {
    float acc2[2][4][4];
    two_layer(Xg, W0s, sb0, W1s, rb, g, q, acc2);
    out_dots(acc2, sb1, sWo, q, sdfv);
#pragma unroll
    for (int i = 0; i < 2; i++)
#pragma unroll
      for (int k = 0; k < 2; k++) sdfv[i][k] = tanhf(sdfv[i][k] + sext[0]);
  }
  {
    float acc2[2][4][4];
    two_layer(Xc, cW0s, scb0, cW1s, rb, g, q, acc2);
    out_dots(acc2, scb1, scWo + 0,  q, rv);
    out_dots(acc2, scb1, scWo + 32, q, gv);
    out_dots(acc2, scb1, scWo + 64, q, bv);
  }

  if (q == 0) {
    float4* out4 = reinterpret_cast<float4*>(P.out);
#pragma unroll
    for (int i = 0; i < 2; i++) {
      int r0 = blockbase + rb + i * 16 + g;
      if (r0 < P.N)
        out4[r0] = make_float4(rv[i][0] + sext[1], gv[i][0] + sext[2],
                               bv[i][0] + sext[3], sdfv[i][0]);
      if (r0 + 8 < P.N)
        out4[r0 + 8] = make_float4(rv[i][1] + sext[1], gv[i][1] + sext[2],
                                   bv[i][1] + sext[3], sdfv[i][1]);
    }
  }
}

constexpr int DEC_SMEM = (2 * BP * XS + 2 * 32 * XS + 2 * 32 * WS1) * 2 + 260 * 4;

}  // namespace

extern "C" void kernel_launch(void* const* d_in, const int* in_sizes, int n_in,
                              void* d_out, int out_size) {
  Pack3 P3;
  for (int i = 0; i < 3; i++) {
    P3.geo[i] = (const float*)d_in[2 + i];
    P3.col[i] = (const float*)d_in[8 + i];
  }
  pack512_all<<<6144, 128>>>(P3);
  static const long long offs1[3] = {OFF_XY1, OFF_XZ1, OFF_YZ1};
  for (int i = 0; i < 3; i++) {
    pack_pair<<<8192, 128>>>((const float*)d_in[5 + i], (const float*)d_in[11 + i],
                             offs1[i], 1048576);
  }

  const float* p = (const float*)d_in[0];
  const float* bound = (const float*)d_in[1];
  int N = in_sizes[0] / 3;

  gather_kernel<<<(4 * N + 255) / 256, 256>>>(p, bound, N);

  MlpP P;
  P.p = p; P.bound = bound;
  P.W0  = (const float*)d_in[14]; P.b0  = (const float*)d_in[15];
  P.W1  = (const float*)d_in[16]; P.b1  = (const float*)d_in[17];
  P.Wo  = (const float*)d_in[18]; P.bo  = (const float*)d_in[19];
  P.cW0 = (const float*)d_in[20]; P.cb0 = (const float*)d_in[21];
  P.cW1 = (const float*)d_in[22]; P.cb1 = (const float*)d_in[23];
  P.cWo = (const float*)d_in[24]; P.cbo = (const float*)d_in[25];
  P.out = (float*)d_out;
  P.N = N;

  cudaFuncSetAttribute(decode_kernel, cudaFuncAttributeMaxDynamicSharedMemorySize, DEC_SMEM);
  decode_kernel<<<(N + BP - 1) / BP, BP, DEC_SMEM>>>(P);
}